// round 13
// baseline (speedup 1.0000x reference)
#include <cuda_runtime.h>
#include <cuda_bf16.h>
#include <cuda_fp16.h>

#define HIDDEN 16
#define SPLITS 4
#define MAX_V  65536
#define MAX_B  1024

// Scratch (device globals — no allocation allowed)
__device__ __half g_gu_h[MAX_V * HIDDEN];              // fp16 per-vocab g*tanh(u)
__device__ float  g_partial[SPLITS * MAX_B * HIDDEN];  // fp32 partial memory sums

// ---------------------------------------------------------------------------
// helpers
// ---------------------------------------------------------------------------
__device__ __forceinline__ unsigned long long pack2(float a, float b) {
    unsigned long long r;
    asm("mov.b64 %0, {%1, %2};" : "=l"(r)
        : "r"(__float_as_uint(a)), "r"(__float_as_uint(b)));
    return r;
}
__device__ __forceinline__ void unpack2(unsigned long long p, float& a, float& b) {
    unsigned int lo, hi;
    asm("mov.b64 {%0, %1}, %2;" : "=r"(lo), "=r"(hi) : "l"(p));
    a = __uint_as_float(lo); b = __uint_as_float(hi);
}
__device__ __forceinline__ unsigned long long fma2(unsigned long long a,
                                                   unsigned long long b,
                                                   unsigned long long c) {
    unsigned long long d;
    asm("fma.rn.f32x2 %0, %1, %2, %3;" : "=l"(d) : "l"(a), "l"(b), "l"(c));
    return d;
}
__device__ __forceinline__ unsigned long long add2(unsigned long long a,
                                                   unsigned long long b) {
    unsigned long long d;
    asm("add.rn.f32x2 %0, %1, %2;" : "=l"(d) : "l"(a), "l"(b));
    return d;
}
__device__ __forceinline__ void stcs1(float* p, float a) {
    asm volatile("st.global.cs.f32 [%0], %1;" :: "l"(p), "f"(a) : "memory");
}
__device__ __forceinline__ void stcs2(float* p, float a, float b) {
    asm volatile("st.global.cs.v2.f32 [%0], {%1, %2};"
                 :: "l"(p), "f"(a), "f"(b) : "memory");
}
__device__ __forceinline__ void stcs4(float* p, float a, float b, float c, float d) {
    asm volatile("st.global.cs.v4.f32 [%0], {%1, %2, %3, %4};"
                 :: "l"(p), "f"(a), "f"(b), "f"(c), "f"(d) : "memory");
}

// FFMA-only tanh (odd Taylor through x^17). |x| <= ~0.7 here; abs err < 5e-6.
__device__ __forceinline__ float tanh_poly(float x) {
    float s = x * x;
    float p =              5.9002744e-04f;
    p = fmaf(p, s, -1.4558300e-03f);
    p = fmaf(p, s,  3.5921280e-03f);
    p = fmaf(p, s, -8.8632355e-03f);
    p = fmaf(p, s,  2.1869488e-02f);
    p = fmaf(p, s, -5.3968254e-02f);
    p = fmaf(p, s,  1.3333333e-01f);
    p = fmaf(p, s, -3.3333333e-01f);
    return fmaf(p * s, x, x);
}

// ---------------------------------------------------------------------------
// Kernel A (R5 verbatim — 7.5us): one thread per (v, k-quad).
// ---------------------------------------------------------------------------
__global__ void __launch_bounds__(256)
precompute_gu(const float* __restrict__ embed,
              const float* __restrict__ Wg,
              const float* __restrict__ bg,
              const float* __restrict__ Wu,
              const float* __restrict__ bu,
              int V)
{
    __shared__ float4 WuS4[HIDDEN * 4];   // [h][kq]
    __shared__ float  WgS[HIDDEN];
    __shared__ float4 buS4[4];
    __shared__ float  bgS;

    int tid = threadIdx.x;
    if (tid < HIDDEN * 4) WuS4[tid] = reinterpret_cast<const float4*>(Wu)[tid];
    if (tid < HIDDEN) WgS[tid] = Wg[tid];
    if (tid < 4) buS4[tid] = reinterpret_cast<const float4*>(bu)[tid];
    if (tid == 0) bgS = bg[0];
    __syncthreads();

    int gidx = blockIdx.x * 256 + tid;
    int v  = gidx >> 2;
    int kq = gidx & 3;
    if (v >= V) return;

    float e[HIDDEN];
    const float4* e4 = reinterpret_cast<const float4*>(embed + (size_t)v * HIDDEN);
    #pragma unroll
    for (int j = 0; j < HIDDEN / 4; j++) {
        float4 t = __ldg(&e4[j]);
        e[4*j+0] = t.x; e[4*j+1] = t.y; e[4*j+2] = t.z; e[4*j+3] = t.w;
    }

    float dg = bgS;
    #pragma unroll
    for (int h = 0; h < HIDDEN; h++) dg = fmaf(e[h], WgS[h], dg);
    float g = fmaf(0.5f, tanh_poly(0.5f * dg), 0.5f);

    float4 acc = buS4[kq];
    #pragma unroll
    for (int h = 0; h < HIDDEN; h++) {
        float4 w = WuS4[h * 4 + kq];
        float eh = e[h];
        acc.x = fmaf(eh, w.x, acc.x);
        acc.y = fmaf(eh, w.y, acc.y);
        acc.z = fmaf(eh, w.z, acc.z);
        acc.w = fmaf(eh, w.w, acc.w);
    }

    __half2 r01 = __floats2half2_rn(g * tanh_poly(acc.x), g * tanh_poly(acc.y));
    __half2 r23 = __floats2half2_rn(g * tanh_poly(acc.z), g * tanh_poly(acc.w));
    uint2 packed;
    packed.x = *reinterpret_cast<unsigned int*>(&r01);
    packed.y = *reinterpret_cast<unsigned int*>(&r23);
    reinterpret_cast<uint2*>(g_gu_h)[(size_t)v * 4 + kq] = packed;
}

// ---------------------------------------------------------------------------
// Kernel B (R5 verbatim — 8.6us; unroll 8, no prefetch): block per (split,b).
// ---------------------------------------------------------------------------
__global__ void accumulate_memory(const int* __restrict__ seq, int B, int T)
{
    int b = blockIdx.x % B;
    int s = blockIdx.x / B;
    int tid = threadIdx.x;
    int c   = tid & 3;       // lane: h range [4c, 4c+4)
    int grp = tid >> 2;      // 0..63 token groups

    int chunk  = (T + SPLITS - 1) / SPLITS;
    int tstart = s * chunk;
    int tend   = min(T, tstart + chunk);

    const int*  srow = seq + (size_t)b * T;
    const uint2* gu2 = reinterpret_cast<const uint2*>(g_gu_h);

    float4 acc = make_float4(0.f, 0.f, 0.f, 0.f);
    #pragma unroll 8
    for (int t = tstart + grp; t < tend; t += 64) {
        int idx = __ldg(&srow[t]);
        uint2 r = __ldg(&gu2[(size_t)idx * 4 + c]);
        float2 f0 = __half22float2(*reinterpret_cast<__half2*>(&r.x));
        float2 f1 = __half22float2(*reinterpret_cast<__half2*>(&r.y));
        acc.x += f0.x; acc.y += f0.y; acc.z += f1.x; acc.w += f1.y;
    }

    __shared__ float4 red[256];
    red[tid] = acc;
    __syncthreads();
    for (int off = 128; off >= 4; off >>= 1) {
        if (tid < off) {
            float4 a = red[tid], o = red[tid + off];
            a.x += o.x; a.y += o.y; a.z += o.z; a.w += o.w;
            red[tid] = a;
        }
        __syncthreads();
    }
    if (tid < 4) {
        float4* p = reinterpret_cast<float4*>(g_partial);
        p[((size_t)s * B + b) * 4 + tid] = red[tid];
    }
}

// ---------------------------------------------------------------------------
// Kernel C: out[b][v] = sum_h memory[b][h] * Wo[h][v] + bo[v]
// Proven frame (BTILE 16, VTILE 1024, 2 blocks/SM) +
//  * 4 CONSECUTIVE v per thread -> vectorized stores where alignment allows
//    ((b*V+v0) mod 4 == b mod 4, compile-time per unrolled b slot)
//  * software-pipelined m row: each LDS.128 reloaded for b+1 right after its
//    last use in b -> full iteration of latency cover, no extra registers.
// ---------------------------------------------------------------------------
#define C_VTILE 1024
#define C_BTILE 16
__global__ void __launch_bounds__(256, 2)
output_gemv(const float* __restrict__ Wo,
            const float* __restrict__ bo,
            float* __restrict__ out,
            int B, int V)
{
    __shared__ float2 memS[C_BTILE * HIDDEN];   // (m,m) per (bl,h), 2KB

    int tid = threadIdx.x;
    int b0  = blockIdx.y * C_BTILE;

    {   // stage m: 256 threads <-> 16 b x 16 h; duplicated (m,m)
        int bl = tid >> 4, h = tid & 15;
        int b = b0 + bl;
        float m = 0.0f;
        if (b < B) {
            const float* p = g_partial + (size_t)b * HIDDEN + h;
            const size_t st = (size_t)B * HIDDEN;
            m = (p[0] + p[st]) + (p[2 * st] + p[3 * st]);
        }
        memS[bl * HIDDEN + h] = make_float2(m, m);
    }

    int v0 = blockIdx.x * C_VTILE + tid * 4;    // 4 consecutive v
    bool ok0 = v0     < V, ok1 = v0 + 1 < V;
    bool ok2 = v0 + 2 < V, ok3 = v0 + 3 < V;
    bool ok4 = ok3;                              // full quad valid

    // Wo columns (scalar loads — Wo rows are NOT 16B-aligned at v0: h*V ≡ h mod 4)
    unsigned long long wp01[HIDDEN], wp23[HIDDEN];
    #pragma unroll
    for (int h = 0; h < HIDDEN; h++) {
        const float* row = Wo + (size_t)h * V;
        float w0 = ok0 ? __ldg(row + v0)     : 0.0f;
        float w1 = ok1 ? __ldg(row + v0 + 1) : 0.0f;
        float w2 = ok2 ? __ldg(row + v0 + 2) : 0.0f;
        float w3 = ok3 ? __ldg(row + v0 + 3) : 0.0f;
        wp01[h] = pack2(w0, w1);
        wp23[h] = pack2(w2, w3);
    }
    unsigned long long bias01 = pack2(ok0 ? __ldg(bo + v0)     : 0.0f,
                                      ok1 ? __ldg(bo + v0 + 1) : 0.0f);
    unsigned long long bias23 = pack2(ok2 ? __ldg(bo + v0 + 2) : 0.0f,
                                      ok3 ? __ldg(bo + v0 + 3) : 0.0f);
    __syncthreads();

    const ulonglong2* mbase = reinterpret_cast<const ulonglong2*>(memS);
    // preload row 0 (8 x LDS.128 broadcast)
    ulonglong2 c0 = mbase[0], c1 = mbase[1], c2 = mbase[2], c3 = mbase[3];
    ulonglong2 c4 = mbase[4], c5 = mbase[5], c6 = mbase[6], c7 = mbase[7];

    int bmax = min(C_BTILE, B - b0);
    #pragma unroll
    for (int bl = 0; bl < C_BTILE; bl++) {
        if (bl >= bmax) break;
        const ulonglong2* nxt = mbase + (((bl + 1) & (C_BTILE - 1)) << 3);

        unsigned long long a01 = bias01, e01 = 0;
        unsigned long long a23 = bias23, e23 = 0;

        a01 = fma2(wp01[0],  c0.x, a01);  a23 = fma2(wp23[0],  c0.x, a23);
        e01 = fma2(wp01[1],  c0.y, e01);  e23 = fma2(wp23[1],  c0.y, e23);
        c0 = nxt[0];
        a01 = fma2(wp01[2],  c1.x, a01);  a23 = fma2(wp23[2],  c1.x, a23);
        e01 = fma2(wp01[3],  c1.y, e01);  e23 = fma2(wp23[3],  c1.y, e23);
        c1 = nxt[1];
        a01 = fma2(wp01[4],  c2.x, a01);  a23 = fma2(wp23[4],  c2.x, a23);
        e01 = fma2(wp01[5],  c2.y, e01);  e23 = fma2(wp23[5],  c2.y, e23);
        c2 = nxt[2];
        a01 = fma2(wp01[6],  c3.x, a01);  a23 = fma2(wp23[6],  c3.x, a23);
        e01 = fma2(wp01[7],  c3.y, e01);  e23 = fma2(wp23[7],  c3.y, e23);
        c3 = nxt[3];
        a01 = fma2(wp01[8],  c4.x, a01);  a23 = fma2(wp23[8],  c4.x, a23);
        e01 = fma2(wp01[9],  c4.y, e01);  e23 = fma2(wp23[9],  c4.y, e23);
        c4 = nxt[4];
        a01 = fma2(wp01[10], c5.x, a01);  a23 = fma2(wp23[10], c5.x, a23);
        e01 = fma2(wp01[11], c5.y, e01);  e23 = fma2(wp23[11], c5.y, e23);
        c5 = nxt[5];
        a01 = fma2(wp01[12], c6.x, a01);  a23 = fma2(wp23[12], c6.x, a23);
        e01 = fma2(wp01[13], c6.y, e01);  e23 = fma2(wp23[13], c6.y, e23);
        c6 = nxt[6];
        a01 = fma2(wp01[14], c7.x, a01);  a23 = fma2(wp23[14], c7.x, a23);
        e01 = fma2(wp01[15], c7.y, e01);  e23 = fma2(wp23[15], c7.y, e23);
        c7 = nxt[7];

        unsigned long long s01 = add2(a01, e01);
        unsigned long long s23 = add2(a23, e23);

        float r0, r1, r2, r3;
        unpack2(s01, r0, r1);
        unpack2(s23, r2, r3);

        int b = b0 + bl;                       // b ≡ bl (mod 4): b0 multiple of 16
        float* ad = out + (size_t)b * V + v0;  // (b*V+v0) mod 4 == bl mod 4
        if (ok4) {
            if ((bl & 3) == 0)      stcs4(ad, r0, r1, r2, r3);          // 16B aligned
            else if ((bl & 1) == 0) { stcs2(ad, r0, r1); stcs2(ad + 2, r2, r3); } // 8B
            else { stcs1(ad, r0); stcs1(ad + 1, r1); stcs1(ad + 2, r2); stcs1(ad + 3, r3); }
        } else {
            if (ok0) stcs1(ad, r0);
            if (ok1) stcs1(ad + 1, r1);
            if (ok2) stcs1(ad + 2, r2);
            if (ok3) stcs1(ad + 3, r3);
        }
    }
}

// ---------------------------------------------------------------------------
extern "C" void kernel_launch(void* const* d_in, const int* in_sizes, int n_in,
                              void* d_out, int out_size)
{
    const int*   seq   = (const int*)  d_in[0];
    const float* embed = (const float*)d_in[1];
    const float* Wg    = (const float*)d_in[2];
    const float* bg    = (const float*)d_in[3];
    const float* Wu    = (const float*)d_in[4];
    const float* bu    = (const float*)d_in[5];
    const float* Wo    = (const float*)d_in[6];
    const float* bo    = (const float*)d_in[7];
    float*       out   = (float*)d_out;

    int V = in_sizes[7];
    int B = out_size / V;
    int T = in_sizes[0] / B;

    int a_threads = V * 4;
    precompute_gu<<<(a_threads + 255) / 256, 256>>>(embed, Wg, bg, Wu, bu, V);

    accumulate_memory<<<SPLITS * B, 256>>>(seq, B, T);

    dim3 gridC((V + C_VTILE - 1) / C_VTILE, (B + C_BTILE - 1) / C_BTILE);
    output_gemv<<<gridC, 256>>>(Wo, bo, out, B, V);
}

// round 14
// speedup vs baseline: 1.0557x; 1.0557x over previous
#include <cuda_runtime.h>
#include <cuda_bf16.h>
#include <cuda_fp16.h>

#define HIDDEN 16
#define SPLITS 4
#define MAX_V  65536
#define MAX_B  1024

// Scratch (device globals — no allocation allowed)
__device__ __half g_gu_h[MAX_V * HIDDEN];              // fp16 per-vocab g*tanh(u)
__device__ float  g_partial[SPLITS * MAX_B * HIDDEN];  // fp32 partial memory sums

// ---------------------------------------------------------------------------
// helpers
// ---------------------------------------------------------------------------
__device__ __forceinline__ unsigned long long pack2(float a, float b) {
    unsigned long long r;
    asm("mov.b64 %0, {%1, %2};" : "=l"(r)
        : "r"(__float_as_uint(a)), "r"(__float_as_uint(b)));
    return r;
}
__device__ __forceinline__ void unpack2(unsigned long long p, float& a, float& b) {
    unsigned int lo, hi;
    asm("mov.b64 {%0, %1}, %2;" : "=r"(lo), "=r"(hi) : "l"(p));
    a = __uint_as_float(lo); b = __uint_as_float(hi);
}
__device__ __forceinline__ unsigned long long fma2(unsigned long long a,
                                                   unsigned long long b,
                                                   unsigned long long c) {
    unsigned long long d;
    asm("fma.rn.f32x2 %0, %1, %2, %3;" : "=l"(d) : "l"(a), "l"(b), "l"(c));
    return d;
}
__device__ __forceinline__ unsigned long long add2(unsigned long long a,
                                                   unsigned long long b) {
    unsigned long long d;
    asm("add.rn.f32x2 %0, %1, %2;" : "=l"(d) : "l"(a), "l"(b));
    return d;
}

// FFMA-only tanh (odd Taylor through x^17). |x| <= ~0.7 here; abs err < 5e-6.
__device__ __forceinline__ float tanh_poly(float x) {
    float s = x * x;
    float p =              5.9002744e-04f;
    p = fmaf(p, s, -1.4558300e-03f);
    p = fmaf(p, s,  3.5921280e-03f);
    p = fmaf(p, s, -8.8632355e-03f);
    p = fmaf(p, s,  2.1869488e-02f);
    p = fmaf(p, s, -5.3968254e-02f);
    p = fmaf(p, s,  1.3333333e-01f);
    p = fmaf(p, s, -3.3333333e-01f);
    return fmaf(p * s, x, x);
}

// ---------------------------------------------------------------------------
// Kernel A (R5 verbatim — 7.5us): one thread per (v, k-quad).
// ---------------------------------------------------------------------------
__global__ void __launch_bounds__(256)
precompute_gu(const float* __restrict__ embed,
              const float* __restrict__ Wg,
              const float* __restrict__ bg,
              const float* __restrict__ Wu,
              const float* __restrict__ bu,
              int V)
{
    __shared__ float4 WuS4[HIDDEN * 4];   // [h][kq]
    __shared__ float  WgS[HIDDEN];
    __shared__ float4 buS4[4];
    __shared__ float  bgS;

    int tid = threadIdx.x;
    if (tid < HIDDEN * 4) WuS4[tid] = reinterpret_cast<const float4*>(Wu)[tid];
    if (tid < HIDDEN) WgS[tid] = Wg[tid];
    if (tid < 4) buS4[tid] = reinterpret_cast<const float4*>(bu)[tid];
    if (tid == 0) bgS = bg[0];
    __syncthreads();

    int gidx = blockIdx.x * 256 + tid;
    int v  = gidx >> 2;
    int kq = gidx & 3;
    if (v >= V) return;

    float e[HIDDEN];
    const float4* e4 = reinterpret_cast<const float4*>(embed + (size_t)v * HIDDEN);
    #pragma unroll
    for (int j = 0; j < HIDDEN / 4; j++) {
        float4 t = __ldg(&e4[j]);
        e[4*j+0] = t.x; e[4*j+1] = t.y; e[4*j+2] = t.z; e[4*j+3] = t.w;
    }

    float dg = bgS;
    #pragma unroll
    for (int h = 0; h < HIDDEN; h++) dg = fmaf(e[h], WgS[h], dg);
    float g = fmaf(0.5f, tanh_poly(0.5f * dg), 0.5f);

    float4 acc = buS4[kq];
    #pragma unroll
    for (int h = 0; h < HIDDEN; h++) {
        float4 w = WuS4[h * 4 + kq];
        float eh = e[h];
        acc.x = fmaf(eh, w.x, acc.x);
        acc.y = fmaf(eh, w.y, acc.y);
        acc.z = fmaf(eh, w.z, acc.z);
        acc.w = fmaf(eh, w.w, acc.w);
    }

    __half2 r01 = __floats2half2_rn(g * tanh_poly(acc.x), g * tanh_poly(acc.y));
    __half2 r23 = __floats2half2_rn(g * tanh_poly(acc.z), g * tanh_poly(acc.w));
    uint2 packed;
    packed.x = *reinterpret_cast<unsigned int*>(&r01);
    packed.y = *reinterpret_cast<unsigned int*>(&r23);
    reinterpret_cast<uint2*>(g_gu_h)[(size_t)v * 4 + kq] = packed;
}

// ---------------------------------------------------------------------------
// Kernel B (R5 verbatim — 8.6us): block per (split, b), fp16 gather,
// fp32 accumulate, block reduction, unroll 8.
// ---------------------------------------------------------------------------
__global__ void accumulate_memory(const int* __restrict__ seq, int B, int T)
{
    int b = blockIdx.x % B;
    int s = blockIdx.x / B;
    int tid = threadIdx.x;
    int c   = tid & 3;       // lane: h range [4c, 4c+4)
    int grp = tid >> 2;      // 0..63 token groups

    int chunk  = (T + SPLITS - 1) / SPLITS;
    int tstart = s * chunk;
    int tend   = min(T, tstart + chunk);

    const int*  srow = seq + (size_t)b * T;
    const uint2* gu2 = reinterpret_cast<const uint2*>(g_gu_h);

    float4 acc = make_float4(0.f, 0.f, 0.f, 0.f);
    #pragma unroll 8
    for (int t = tstart + grp; t < tend; t += 64) {
        int idx = __ldg(&srow[t]);
        uint2 r = __ldg(&gu2[(size_t)idx * 4 + c]);
        float2 f0 = __half22float2(*reinterpret_cast<__half2*>(&r.x));
        float2 f1 = __half22float2(*reinterpret_cast<__half2*>(&r.y));
        acc.x += f0.x; acc.y += f0.y; acc.z += f1.x; acc.w += f1.y;
    }

    __shared__ float4 red[256];
    red[tid] = acc;
    __syncthreads();
    for (int off = 128; off >= 4; off >>= 1) {
        if (tid < off) {
            float4 a = red[tid], o = red[tid + off];
            a.x += o.x; a.y += o.y; a.z += o.z; a.w += o.w;
            red[tid] = a;
        }
        __syncthreads();
    }
    if (tid < 4) {
        float4* p = reinterpret_cast<float4*>(g_partial);
        p[((size_t)s * B + b) * 4 + tid] = red[tid];
    }
}

// ---------------------------------------------------------------------------
// Kernel C — CONTROLLED OCCUPANCY EXPERIMENT:
// R10's exact inner loop ((m,m)-dedup shared, 8 broadcast LDS.128 -> fma2,
// no per-b packs), only change: 2 v-lanes/thread (VTILE 512, wp = 32 regs)
// and __launch_bounds__(256,4) -> 4 blocks/SM, 32 warps/SM (vs 16).
// ---------------------------------------------------------------------------
#define C_VTILE 512
#define C_BTILE 16
__global__ void __launch_bounds__(256, 4)
output_gemv(const float* __restrict__ Wo,
            const float* __restrict__ bo,
            float* __restrict__ out,
            int B, int V)
{
    __shared__ float2 memS[C_BTILE * HIDDEN];   // (m,m) per (bl,h), 2KB

    int tid = threadIdx.x;
    int b0  = blockIdx.y * C_BTILE;

    {   // stage m: 256 threads <-> 16 b x 16 h; duplicated (m,m)
        int bl = tid >> 4, h = tid & 15;
        int b = b0 + bl;
        float m = 0.0f;
        if (b < B) {
            const float* p = g_partial + (size_t)b * HIDDEN + h;
            const size_t st = (size_t)B * HIDDEN;
            m = (p[0] + p[st]) + (p[2 * st] + p[3 * st]);
        }
        memS[bl * HIDDEN + h] = make_float2(m, m);
    }

    int v0 = blockIdx.x * C_VTILE + tid;
    int v1 = v0 + 256;
    bool ok0 = v0 < V, ok1 = v1 < V;

    // Wo pair (v0, v1) per h — 16 u64 = 32 registers
    unsigned long long wp[HIDDEN];
    #pragma unroll
    for (int h = 0; h < HIDDEN; h++) {
        const float* row = Wo + (size_t)h * V;
        float w0 = ok0 ? __ldg(row + v0) : 0.0f;
        float w1 = ok1 ? __ldg(row + v1) : 0.0f;
        wp[h] = pack2(w0, w1);
    }
    unsigned long long bias = pack2(ok0 ? __ldg(bo + v0) : 0.0f,
                                    ok1 ? __ldg(bo + v1) : 0.0f);
    __syncthreads();

    const ulonglong2* mbase = reinterpret_cast<const ulonglong2*>(memS);
    int bmax = min(C_BTILE, B - b0);

    for (int bl = 0; bl < bmax; bl++) {
        const ulonglong2* mrow = mbase + bl * (HIDDEN / 2);
        unsigned long long aE = bias, aO = 0;
        #pragma unroll
        for (int hh = 0; hh < HIDDEN / 2; hh++) {
            ulonglong2 mp = mrow[hh];          // LDS.128 broadcast: (m,m),(m',m')
            aE = fma2(wp[2*hh],     mp.x, aE);
            aO = fma2(wp[2*hh + 1], mp.y, aO);
        }
        unsigned long long s = add2(aE, aO);

        float r0, r1;
        unpack2(s, r0, r1);
        float* orow = out + (size_t)(b0 + bl) * V;
        if (ok0) orow[v0] = r0;
        if (ok1) orow[v1] = r1;
    }
}

// ---------------------------------------------------------------------------
extern "C" void kernel_launch(void* const* d_in, const int* in_sizes, int n_in,
                              void* d_out, int out_size)
{
    const int*   seq   = (const int*)  d_in[0];
    const float* embed = (const float*)d_in[1];
    const float* Wg    = (const float*)d_in[2];
    const float* bg    = (const float*)d_in[3];
    const float* Wu    = (const float*)d_in[4];
    const float* bu    = (const float*)d_in[5];
    const float* Wo    = (const float*)d_in[6];
    const float* bo    = (const float*)d_in[7];
    float*       out   = (float*)d_out;

    int V = in_sizes[7];
    int B = out_size / V;
    int T = in_sizes[0] / B;

    int a_threads = V * 4;
    precompute_gu<<<(a_threads + 255) / 256, 256>>>(embed, Wg, bg, Wu, bu, V);

    accumulate_memory<<<SPLITS * B, 256>>>(seq, B, T);

    dim3 gridC((V + C_VTILE - 1) / C_VTILE, (B + C_BTILE - 1) / C_BTILE);
    output_gemv<<<gridC, 256>>>(Wo, bo, out, B, V);
}

// round 16
// speedup vs baseline: 1.1089x; 1.0504x over previous
#include <cuda_runtime.h>
#include <cuda_bf16.h>
#include <cuda_fp16.h>

#define HIDDEN 16
#define SPLITS 4
#define MAX_V  65536
#define MAX_B  1024

// Scratch (device globals — no allocation allowed)
__device__ __half g_gu_h[MAX_V * HIDDEN];              // fp16 per-vocab g*tanh(u)
__device__ float  g_partial[SPLITS * MAX_B * HIDDEN];  // fp32 partial memory sums

// ---------------------------------------------------------------------------
// helpers
// ---------------------------------------------------------------------------
__device__ __forceinline__ unsigned long long pack2(float a, float b) {
    unsigned long long r;
    asm("mov.b64 %0, {%1, %2};" : "=l"(r)
        : "r"(__float_as_uint(a)), "r"(__float_as_uint(b)));
    return r;
}
__device__ __forceinline__ void unpack2(unsigned long long p, float& a, float& b) {
    unsigned int lo, hi;
    asm("mov.b64 {%0, %1}, %2;" : "=r"(lo), "=r"(hi) : "l"(p));
    a = __uint_as_float(lo); b = __uint_as_float(hi);
}
__device__ __forceinline__ unsigned long long fma2(unsigned long long a,
                                                   unsigned long long b,
                                                   unsigned long long c) {
    unsigned long long d;
    asm("fma.rn.f32x2 %0, %1, %2, %3;" : "=l"(d) : "l"(a), "l"(b), "l"(c));
    return d;
}
__device__ __forceinline__ unsigned long long add2(unsigned long long a,
                                                   unsigned long long b) {
    unsigned long long d;
    asm("add.rn.f32x2 %0, %1, %2;" : "=l"(d) : "l"(a), "l"(b));
    return d;
}
__device__ __forceinline__ void stcs1(float* p, float v) {
    asm volatile("st.global.cs.f32 [%0], %1;" :: "l"(p), "f"(v) : "memory");
}

// FFMA-only tanh (odd Taylor through x^17). |x| <= ~0.7 here; abs err < 5e-6.
__device__ __forceinline__ float tanh_poly(float x) {
    float s = x * x;
    float p =              5.9002744e-04f;
    p = fmaf(p, s, -1.4558300e-03f);
    p = fmaf(p, s,  3.5921280e-03f);
    p = fmaf(p, s, -8.8632355e-03f);
    p = fmaf(p, s,  2.1869488e-02f);
    p = fmaf(p, s, -5.3968254e-02f);
    p = fmaf(p, s,  1.3333333e-01f);
    p = fmaf(p, s, -3.3333333e-01f);
    return fmaf(p * s, x, x);
}

// ---------------------------------------------------------------------------
// Kernel A: one thread per (v, k-quad), embed rows staged through shared.
// One coalesced LDG.128 + STS.128 per thread (~32 L1 wavefronts/block)
// instead of 4 scattered LDG.128 per thread (~1000 wavefronts/block).
// E_STRIDE=20 floats (80B): 16B-aligned row starts, conflict-free broadcast.
// FIX vs R15: eS must be 16B-aligned for the float4 accesses.
// ---------------------------------------------------------------------------
#define E_STRIDE 20
__global__ void __launch_bounds__(256)
precompute_gu(const float* __restrict__ embed,
              const float* __restrict__ Wg,
              const float* __restrict__ bg,
              const float* __restrict__ Wu,
              const float* __restrict__ bu,
              int V)
{
    __shared__ float4 WuS4[HIDDEN * 4];   // [h][kq]
    __shared__ float  WgS[HIDDEN];
    __shared__ float4 buS4[4];
    __shared__ float  bgS;
    __shared__ __align__(16) float eS[64 * E_STRIDE];  // 64 rows, padded, 5.1KB

    int tid = threadIdx.x;
    if (tid < HIDDEN * 4) WuS4[tid] = reinterpret_cast<const float4*>(Wu)[tid];
    if (tid < HIDDEN) WgS[tid] = Wg[tid];
    if (tid < 4) buS4[tid] = reinterpret_cast<const float4*>(bu)[tid];
    if (tid == 0) bgS = bg[0];

    // ---- cooperative stage: thread -> (row = tid>>2, quad j = tid&3) ----
    {
        int row = tid >> 2;
        int j   = tid & 3;
        int v   = blockIdx.x * 64 + row;
        if (v < V) {
            float4 t = __ldg(reinterpret_cast<const float4*>(
                                 embed + (size_t)v * HIDDEN) + j);
            *reinterpret_cast<float4*>(&eS[row * E_STRIDE + j * 4]) = t;
        }
    }
    __syncthreads();

    int gidx = blockIdx.x * 256 + tid;
    int v  = gidx >> 2;
    int kq = gidx & 3;
    if (v >= V) return;

    // read own row from shared (4-way broadcast groups, conflict-free)
    const float* erow = &eS[(tid >> 2) * E_STRIDE];
    float e[HIDDEN];
    #pragma unroll
    for (int j = 0; j < 4; j++) {
        float4 t = *reinterpret_cast<const float4*>(erow + j * 4);
        e[4*j+0] = t.x; e[4*j+1] = t.y; e[4*j+2] = t.z; e[4*j+3] = t.w;
    }

    float dg = bgS;
    #pragma unroll
    for (int h = 0; h < HIDDEN; h++) dg = fmaf(e[h], WgS[h], dg);
    float g = fmaf(0.5f, tanh_poly(0.5f * dg), 0.5f);

    float4 acc = buS4[kq];
    #pragma unroll
    for (int h = 0; h < HIDDEN; h++) {
        float4 w = WuS4[h * 4 + kq];
        float eh = e[h];
        acc.x = fmaf(eh, w.x, acc.x);
        acc.y = fmaf(eh, w.y, acc.y);
        acc.z = fmaf(eh, w.z, acc.z);
        acc.w = fmaf(eh, w.w, acc.w);
    }

    __half2 r01 = __floats2half2_rn(g * tanh_poly(acc.x), g * tanh_poly(acc.y));
    __half2 r23 = __floats2half2_rn(g * tanh_poly(acc.z), g * tanh_poly(acc.w));
    uint2 packed;
    packed.x = *reinterpret_cast<unsigned int*>(&r01);
    packed.y = *reinterpret_cast<unsigned int*>(&r23);
    reinterpret_cast<uint2*>(g_gu_h)[(size_t)v * 4 + kq] = packed;
}

// ---------------------------------------------------------------------------
// Kernel B (R5 verbatim — 8.6us): block per (split, b), fp16 gather,
// fp32 accumulate, block reduction, unroll 8.
// ---------------------------------------------------------------------------
__global__ void accumulate_memory(const int* __restrict__ seq, int B, int T)
{
    int b = blockIdx.x % B;
    int s = blockIdx.x / B;
    int tid = threadIdx.x;
    int c   = tid & 3;       // lane: h range [4c, 4c+4)
    int grp = tid >> 2;      // 0..63 token groups

    int chunk  = (T + SPLITS - 1) / SPLITS;
    int tstart = s * chunk;
    int tend   = min(T, tstart + chunk);

    const int*  srow = seq + (size_t)b * T;
    const uint2* gu2 = reinterpret_cast<const uint2*>(g_gu_h);

    float4 acc = make_float4(0.f, 0.f, 0.f, 0.f);
    #pragma unroll 8
    for (int t = tstart + grp; t < tend; t += 64) {
        int idx = __ldg(&srow[t]);
        uint2 r = __ldg(&gu2[(size_t)idx * 4 + c]);
        float2 f0 = __half22float2(*reinterpret_cast<__half2*>(&r.x));
        float2 f1 = __half22float2(*reinterpret_cast<__half2*>(&r.y));
        acc.x += f0.x; acc.y += f0.y; acc.z += f1.x; acc.w += f1.y;
    }

    __shared__ float4 red[256];
    red[tid] = acc;
    __syncthreads();
    for (int off = 128; off >= 4; off >>= 1) {
        if (tid < off) {
            float4 a = red[tid], o = red[tid + off];
            a.x += o.x; a.y += o.y; a.z += o.z; a.w += o.w;
            red[tid] = a;
        }
        __syncthreads();
    }
    if (tid < 4) {
        float4* p = reinterpret_cast<float4*>(g_partial);
        p[((size_t)s * B + b) * 4 + tid] = red[tid];
    }
}

// ---------------------------------------------------------------------------
// Kernel C (R10 verbatim — 17.0us, the measured best): BTILE 16, VTILE 1024,
// 4 v-lanes strided 256, wp in regs, (m,m)-dedup shared, 2 blocks/SM.
// ---------------------------------------------------------------------------
#define C_VTILE 1024
#define C_BTILE 16
__global__ void __launch_bounds__(256, 2)
output_gemv(const float* __restrict__ Wo,
            const float* __restrict__ bo,
            float* __restrict__ out,
            int B, int V)
{
    __shared__ float memS[C_BTILE * HIDDEN * 2];   // (m,m) pairs, 2KB

    int tid = threadIdx.x;
    int b0  = blockIdx.y * C_BTILE;

    {   // stage m: sum the 4 split-partials, write duplicated (m,m)
        int bl = tid >> 4, h = tid & 15;
        int b = b0 + bl;
        float m = 0.0f;
        if (b < B) {
            const float* p = g_partial + ((size_t)b) * HIDDEN + h;
            const size_t stride = (size_t)B * HIDDEN;
            m = (p[0] + p[stride]) + (p[2 * stride] + p[3 * stride]);
        }
        reinterpret_cast<float2*>(memS)[tid] = make_float2(m, m);
    }

    int v0 = blockIdx.x * C_VTILE + tid;
    int v1 = v0 + 256, v2 = v0 + 512, v3 = v0 + 768;
    bool ok0 = v0 < V, ok1 = v1 < V, ok2 = v2 < V, ok3 = v3 < V;

    unsigned long long wp01[HIDDEN], wp23[HIDDEN];
    #pragma unroll
    for (int h = 0; h < HIDDEN; h++) {
        const float* row = Wo + (size_t)h * V;
        float w0 = ok0 ? __ldg(row + v0) : 0.0f;
        float w1 = ok1 ? __ldg(row + v1) : 0.0f;
        float w2 = ok2 ? __ldg(row + v2) : 0.0f;
        float w3 = ok3 ? __ldg(row + v3) : 0.0f;
        wp01[h] = pack2(w0, w1);
        wp23[h] = pack2(w2, w3);
    }
    unsigned long long bias01 = pack2(ok0 ? __ldg(bo + v0) : 0.0f,
                                      ok1 ? __ldg(bo + v1) : 0.0f);
    unsigned long long bias23 = pack2(ok2 ? __ldg(bo + v2) : 0.0f,
                                      ok3 ? __ldg(bo + v3) : 0.0f);
    __syncthreads();

    int bmax = min(C_BTILE, B - b0);
    for (int bl = 0; bl < bmax; bl++) {
        const ulonglong2* mrow =
            reinterpret_cast<const ulonglong2*>(memS + bl * HIDDEN * 2);
        unsigned long long a01 = bias01, b01 = 0;
        unsigned long long a23 = bias23, b23 = 0;
        #pragma unroll
        for (int hh = 0; hh < HIDDEN / 2; hh++) {
            ulonglong2 mp = mrow[hh];          // LDS.128 broadcast
            a01 = fma2(wp01[2*hh],     mp.x, a01);
            a23 = fma2(wp23[2*hh],     mp.x, a23);
            b01 = fma2(wp01[2*hh + 1], mp.y, b01);
            b23 = fma2(wp23[2*hh + 1], mp.y, b23);
        }
        unsigned long long s01 = add2(a01, b01);
        unsigned long long s23 = add2(a23, b23);

        float r0, r1, r2, r3;
        unpack2(s01, r0, r1);
        unpack2(s23, r2, r3);
        float* orow = out + (size_t)(b0 + bl) * V;
        if (ok0) stcs1(orow + v0, r0);
        if (ok1) stcs1(orow + v1, r1);
        if (ok2) stcs1(orow + v2, r2);
        if (ok3) stcs1(orow + v3, r3);
    }
}

// ---------------------------------------------------------------------------
extern "C" void kernel_launch(void* const* d_in, const int* in_sizes, int n_in,
                              void* d_out, int out_size)
{
    const int*   seq   = (const int*)  d_in[0];
    const float* embed = (const float*)d_in[1];
    const float* Wg    = (const float*)d_in[2];
    const float* bg    = (const float*)d_in[3];
    const float* Wu    = (const float*)d_in[4];
    const float* bu    = (const float*)d_in[5];
    const float* Wo    = (const float*)d_in[6];
    const float* bo    = (const float*)d_in[7];
    float*       out   = (float*)d_out;

    int V = in_sizes[7];
    int B = out_size / V;
    int T = in_sizes[0] / B;

    int a_threads = V * 4;
    precompute_gu<<<(a_threads + 255) / 256, 256>>>(embed, Wg, bg, Wu, bu, V);

    accumulate_memory<<<SPLITS * B, 256>>>(seq, B, T);

    dim3 gridC((V + C_VTILE - 1) / C_VTILE, (B + C_BTILE - 1) / C_BTILE);
    output_gemv<<<gridC, 256>>>(Wo, bo, out, B, V);
}